// round 6
// baseline (speedup 1.0000x reference)
#include <cuda_runtime.h>
#include <cuda_bf16.h>

#define TPB   256
#define EPS   6.0e-5f      // edge window in u-units (__log2f u-error ~1.5e-5)

// out[i] = bins[ clip(searchsorted_right(bins, max(logit(x), bins[0])) - 1, 0, 63) ]
// bins = linspace(-6, 6, 64): uniform, step 12/63.
//   u = (lg2(x) - lg2(1-x)) * (ln2*5.25) + 31.5
//   idx = clamp(floor(u), 0, 63);  out = idx*(12/63) - 6
// Elements with frac(u) within EPS of an integer edge are recomputed exactly
// (libdevice logf + searchsorted fixup against the true bins array).

__device__ __forceinline__ float slow_val(float x, const float* __restrict__ bins) {
    float s    = logf(x) - logf(1.0f - x);
    float sbar = fmaxf(s, __ldg(bins));
    float uu   = (sbar + 6.0f) * (63.0f / 12.0f);
    int i = (int)floorf(uu);
    i = i < 0 ? 0 : (i > 63 ? 63 : i);
    if (sbar < __ldg(bins + i))                      i -= 1;
    else if (i < 63 && sbar >= __ldg(bins + i + 1))  i += 1;
    return __ldg(bins + i);
}

__device__ __forceinline__ float fast_u(float x) {
    const float KU = 0.6931471805599453f * 5.25f;   // ln2 * 63/12
    return fmaf(__log2f(x) - __log2f(1.0f - x), KU, 31.5f);
}

#define ELEM(XV, VOUT, ACC) do {                                          \
    float _u  = fast_u(XV);                                               \
    float _fu = floorf(_u);                                               \
    float _t  = (_u - _fu) - 0.5f;                                        \
    ACC = fmaxf(ACC, fabsf(_t));                                          \
    VOUT = fmaf(fminf(fmaxf(_fu, 0.0f), 63.0f), 12.0f / 63.0f, -6.0f);    \
} while (0)

#define FIX(XV, VOUT) do {                                                \
    float _u  = fast_u(XV);                                               \
    float _fr = _u - floorf(_u);                                          \
    if (_fr <= EPS || _fr >= 1.0f - EPS) VOUT = slow_val(XV, bins);       \
} while (0)

// Persistent single-wave kernel: grid-stride over float4s, minimal live set.
__global__ __launch_bounds__(TPB, 8)
void logodds_persist_kernel(const float* __restrict__ Xs,
                            const float* __restrict__ bins,
                            float* __restrict__ out,
                            int n4) {
    const float4* X4 = reinterpret_cast<const float4*>(Xs);
    float4*       O4 = reinterpret_cast<float4*>(out);
    int stride = gridDim.x * TPB;

    for (int i = blockIdx.x * TPB + threadIdx.x; i < n4; i += stride) {
        float4 x = X4[i];
        float acc = 0.0f;
        float4 r;
        ELEM(x.x, r.x, acc);
        ELEM(x.y, r.y, acc);
        ELEM(x.z, r.z, acc);
        ELEM(x.w, r.w, acc);
        O4[i] = r;
        if (acc >= 0.5f - EPS) {          // rare: ~5e-4 of iterations
            FIX(x.x, r.x);
            FIX(x.y, r.y);
            FIX(x.z, r.z);
            FIX(x.w, r.w);
            O4[i] = r;
        }
    }
}

// Generic fallback for the scalar tail (n % 4 elements).
__global__ __launch_bounds__(TPB)
void logodds_tail_kernel(const float* __restrict__ Xs,
                         const float* __restrict__ bins,
                         float* __restrict__ out,
                         int start, int n) {
    int i = start + blockIdx.x * blockDim.x + threadIdx.x;
    if (i < n) {
        float x  = Xs[i];
        float u  = fast_u(x);
        float fu = floorf(u);
        float fr = u - fu;
        float v  = fmaf(fminf(fmaxf(fu, 0.0f), 63.0f), 12.0f / 63.0f, -6.0f);
        if (fr <= EPS || fr >= 1.0f - EPS) v = slow_val(x, bins);
        out[i] = v;
    }
}

extern "C" void kernel_launch(void* const* d_in, const int* in_sizes, int n_in,
                              void* d_out, int out_size) {
    const float* Xs   = (const float*)d_in[0];
    const float* bins = (const float*)d_in[1];
    float* out        = (float*)d_out;
    int n = in_sizes[0];

    int n4 = n >> 2;
    if (n4 > 0) {
        // one wave: 152 SMs x 8 blocks (launch_bounds guarantees occ 8)
        int grid = 152 * 8;
        int need = (n4 + TPB - 1) / TPB;
        if (grid > need) grid = need;
        logodds_persist_kernel<<<grid, TPB>>>(Xs, bins, out, n4);
    }
    int tail_start = n4 << 2;
    int trem = n - tail_start;
    if (trem > 0) {
        logodds_tail_kernel<<<1, TPB>>>(Xs, bins, out, tail_start, n);
    }
}